// round 2
// baseline (speedup 1.0000x reference)
#include <cuda_runtime.h>
#include <cuda_bf16.h>
#include <math.h>

// CropRoi: f (B=4, C=64, 32,32,32) f32; proposals (N,8) [b, score, cx,cy,cz, sx,sy,sz]
// out (N, C, 7,7,7) f32. dims_max = 128/4 = 32 per axis. R=7, K cap=6.

#define R_BINS 7
#define C_CH   64
#define FS     32
#define DIMMAX 32
#define KCAP   6

__global__ void crop_roi_kernel(const float* __restrict__ f,
                                const float* __restrict__ props,
                                float* __restrict__ out,
                                int total, int n_props) {
    int idx = blockIdx.x * blockDim.x + threadIdx.x;
    if (idx >= total) return;

    int k = idx % R_BINS;
    int t = idx / R_BINS;
    int j = t % R_BINS;
    t /= R_BINS;
    int i = t % R_BINS;
    t /= R_BINS;
    int c = t % C_CH;
    int n = t / C_CH;

    const float* p = props + (size_t)n * 8;
    int b = (int)p[0];

    int s[3], e[3];
#pragma unroll
    for (int ax = 0; ax < 3; ax++) {
        float center = __ldg(p + 2 + ax);
        float side   = __ldg(p + 5 + ax);
        // /4 and /2 are exact in fp32 (powers of two), matching jnp arithmetic
        int c0 = (int)floorf((center - 0.5f * side) * 0.25f);
        int c1 = (int)ceilf ((center + 0.5f * side) * 0.25f);
        c0 = max(c0, 0);
        c1 = min(c1, DIMMAX);
        int L = c1 - c0;
        int bi = (ax == 0) ? i : (ax == 1) ? j : k;
        int ss = c0 + (bi * L) / R_BINS;                 // floor div, L>=0
        int ee = c0 + ((bi + 1) * L + R_BINS - 1) / R_BINS; // ceil div
        ee = min(ee, ss + KCAP);                         // reference window cap K
        s[ax] = ss;
        e[ax] = ee;
    }

    const float* base = f + (((size_t)b * C_CH + c) * (FS * FS * FS));
    float m = -3.402823466e+38f;  // finfo(float32).min — matches reference fill
    for (int d = s[0]; d < e[0]; d++) {
        const float* pd = base + d * (FS * FS);
        for (int h = s[1]; h < e[1]; h++) {
            const float* ph = pd + h * FS;
            for (int w = s[2]; w < e[2]; w++) {
                m = fmaxf(m, __ldg(ph + w));
            }
        }
    }
    out[idx] = m;
}

extern "C" void kernel_launch(void* const* d_in, const int* in_sizes, int n_in,
                              void* d_out, int out_size) {
    const float* f     = (const float*)d_in[0];
    // d_in[1] = inputs: only shape matters (128^3 -> dims_max=32), unused at runtime
    const float* props = (const float*)d_in[2];
    // d_in[3] = cls_ind: unused by reference computation
    float* out = (float*)d_out;

    int n_props = in_sizes[2] / 8;
    int total = n_props * C_CH * R_BINS * R_BINS * R_BINS;

    int threads = 256;
    int blocks = (total + threads - 1) / threads;
    crop_roi_kernel<<<blocks, threads>>>(f, props, out, total, n_props);
}

// round 3
// speedup vs baseline: 1.0708x; 1.0708x over previous
#include <cuda_runtime.h>
#include <cuda_bf16.h>
#include <math.h>

// CropRoi: f (B=4, C=64, 32,32,32) f32; proposals (N,8) [b, score, cx,cy,cz, sx,sy,sz]
// out (N, C, 7,7,7) f32. dims_max = 32 per axis. R=7, window cap K=6.

#define R_BINS 7
#define C_CH   64
#define FS     32
#define DIMMAX 32
#define KCAP   6
#define BINS3  343   // 7*7*7

__global__ __launch_bounds__(352) void crop_roi_kernel(
        const float* __restrict__ f,
        const float* __restrict__ props,
        float* __restrict__ out) {
    const int n = blockIdx.x;
    const int c = blockIdx.y;

    __shared__ int sS[3][R_BINS];
    __shared__ int sE[3][R_BINS];
    __shared__ int sB;

    const int tid = threadIdx.x;
    if (tid < 3 * R_BINS) {
        const int ax = tid / R_BINS;
        const int bi = tid % R_BINS;
        const float* p = props + (size_t)n * 8;
        if (tid == 0) sB = (int)p[0];
        float center = __ldg(p + 2 + ax);
        float side   = __ldg(p + 5 + ax);
        // *0.5 and *0.25 exact in fp32 -> matches jnp arithmetic bit-for-bit
        int c0 = (int)floorf((center - 0.5f * side) * 0.25f);
        int c1 = (int)ceilf ((center + 0.5f * side) * 0.25f);
        c0 = max(c0, 0);
        c1 = min(c1, DIMMAX);
        int L  = c1 - c0;                       // L >= 0
        int ss = c0 + (bi * L) / R_BINS;        // floor div
        int ee = c0 + ((bi + 1) * L + R_BINS - 1) / R_BINS; // ceil div
        ee = min(ee, ss + KCAP);                // reference window cap K
        sS[ax][bi] = ss;
        sE[ax][bi] = ee;
    }
    __syncthreads();

    if (tid >= BINS3) return;

    const int k = tid % R_BINS;
    const int t = tid / R_BINS;
    const int j = t % R_BINS;
    const int i = t / R_BINS;

    const int sd = sS[0][i], ed = sE[0][i];
    const int sh = sS[1][j], eh = sE[1][j];
    const int sw = sS[2][k], ew = sE[2][k];

    const float* base = f + (((size_t)sB * C_CH + c) << 15);  // 32*32*32 = 32768

    float m = -3.402823466e+38f;   // finfo(float32).min
    for (int d = sd; d < ed; d++) {
        const float* pd = base + (d << 10);
        for (int h = sh; h < eh; h++) {
            const float* ph = pd + (h << 5);
            for (int w = sw; w < ew; w++) {
                m = fmaxf(m, __ldg(ph + w));
            }
        }
    }

    out[((size_t)n * C_CH + c) * BINS3 + tid] = m;
}

extern "C" void kernel_launch(void* const* d_in, const int* in_sizes, int n_in,
                              void* d_out, int out_size) {
    const float* f     = (const float*)d_in[0];
    const float* props = (const float*)d_in[2];
    float* out = (float*)d_out;

    int n_props = in_sizes[2] / 8;

    dim3 grid(n_props, C_CH);
    crop_roi_kernel<<<grid, 352>>>(f, props, out);
}